// round 13
// baseline (speedup 1.0000x reference)
#include <cuda_runtime.h>
#include <cuda_fp16.h>
#include <cstdint>
#include <cstddef>

#define N_TOK 131072
#define DIM   256
#define NCODE 1024
#define HW    4096
#define DECAY 0.9f
#define OMD   0.1f
#define COMMIT 0.25f
#define EPSV  1e-5

#define LOSS_OFF   33554432
#define IDX_OFF    33554433
#define NEWEMB_OFF 33685505
#define NCS_OFF    33947649
#define NEMA_OFF   33948673

#define RESC_CAP  131072
#define RESC2_CAP 32768
#define TAU1 6e-2f
#define TAU2 4e-3f

__device__ __half g_ehS[NCODE * DIM];   // pre-swizzled blocked [tile][chunk][row][64]
__device__ float  g_e2[NCODE];
__device__ int    g_idx[N_TOK];
__device__ float  g_cnt[NCODE];
__device__ float  g_dw[DIM * NCODE];
__device__ double g_loss;
__device__ float  g_sinv[NCODE];
__device__ int    g_rc1, g_rl1[RESC_CAP];
__device__ int    g_rc2, g_rl2[RESC2_CAP];

__device__ __forceinline__ uint32_t s2u(const void* p) {
    uint32_t a;
    asm("{ .reg .u64 t; cvta.to.shared.u64 t, %1; cvt.u32.u64 %0, t; }" : "=r"(a) : "l"(p));
    return a;
}

// ---- prep: zero scratch ----
__global__ void prep_kernel()
{
    int i = blockIdx.x * 256 + threadIdx.x;      // 0..262143
    if (i < DIM * NCODE) g_dw[i] = 0.0f;
    if (i < NCODE) { g_cnt[i] = 0.0f; g_e2[i] = 0.0f; }
    if (i == 0) { g_loss = 0.0; g_rc1 = 0; g_rc2 = 0; }
}

// ---- embed: [d][k] -> fp16 hi pre-swizzled blocked, plus e2 partials ----
__global__ void conv_e_kernel(const float* __restrict__ embed)
{
    __shared__ float t[64][33];
    int k0 = blockIdx.x * 32, d0 = blockIdx.y * 64;
    int tx = threadIdx.x, ty = threadIdx.y;   // (32, 8); warp = fixed ty
    #pragma unroll
    for (int i = 0; i < 8; i++) {
        int dd = ty + 8 * i;
        t[dd][tx] = embed[(size_t)(d0 + dd) * NCODE + k0 + tx];
    }
    __syncthreads();
    #pragma unroll
    for (int i = 0; i < 4; i++) {
        int j = ty + 8 * i, c = tx, k = k0 + j, d = d0 + 2 * c;
        float v0 = t[2*c][j], v1 = t[2*c+1][j];
        __half h0 = __float2half(v0), h1 = __float2half(v1);
        uint32_t hh = (uint32_t)__half_as_ushort(h0) | ((uint32_t)__half_as_ushort(h1) << 16);
        uint32_t blk = (uint32_t)(k >> 7) * 4u + (uint32_t)(d >> 6);
        uint32_t row = (uint32_t)(k & 127);
        uint32_t off = blk * 16384u + row * 128u
                     + ((((uint32_t)(d & 63) >> 3) ^ (row & 7)) * 16u) + (uint32_t)(d & 7) * 2u;
        *(uint32_t*)((char*)g_ehS + off) = hh;
        float p = v0 * v0 + v1 * v1;
        #pragma unroll
        for (int o = 16; o > 0; o >>= 1) p += __shfl_down_sync(0xffffffffu, p, o);
        if (tx == 0) atomicAdd(&g_e2[k], p);
    }
}

// ---- HMMA argmin (single-term estimate): 128 tokens/CTA vs 1024 codes ----
#define SM_B   0
#define SM_A   65536
#define SM_E2  98304
#define SM_PM1 98816
#define SM_PM2 100864
#define SM_PID 102912
#define SM_RM1 104960
#define SM_RM2 105472
#define SM_RID 105984
#define SMEM_TC 106496

#define CPA(dst, src) \
    asm volatile("{ .reg .u64 g; cvta.to.global.u64 g, %1; cp.async.cg.shared.global [%0], [g], 16; }" \
                 :: "r"(dst), "l"(src) : "memory")

__global__ __launch_bounds__(256, 2)
void argmin_hmma(const float* __restrict__ x)
{
    extern __shared__ char smem[];
    uint32_t sb = s2u(smem);
    int tid = threadIdx.x, lane = tid & 31, wid = tid >> 5;
    int mw = wid >> 1, nw = wid & 1;
    int token0 = blockIdx.x * 128;
    int bb0 = token0 >> 12, hw0 = token0 & 4095;
    const float* xb = x + (size_t)bb0 * DIM * HW + hw0;

    {
        int tok = tid & 127, half = tid >> 7;
        for (int i = 0; i < 64; i++) {
            int d0 = half * 2 + 4 * i;
            float v0 = xb[(size_t)d0 * HW + tok];
            float v1 = xb[(size_t)(d0 + 1) * HW + tok];
            __half h0 = __float2half(v0), h1 = __float2half(v1);
            uint32_t hh = (uint32_t)__half_as_ushort(h0) | ((uint32_t)__half_as_ushort(h1) << 16);
            uint32_t off = (uint32_t)(d0 >> 6) * 16384u + (uint32_t)tok * 128u
                         + ((((uint32_t)(d0 & 63) >> 3) ^ (uint32_t)(tok & 7)) * 16u)
                         + (uint32_t)(d0 & 7) * 2u;
            *(uint32_t*)(smem + SM_B + off) = hh;
        }
    }
    if (tid < 128) {
        ((float*)(smem + SM_RM1))[tid] = 3.4e38f;
        ((float*)(smem + SM_RM2))[tid] = 3.4e38f;
        ((int*)(smem + SM_RID))[tid] = 0;
    }
    __syncthreads();

    for (int tile = 0; tile < 8; tile++) {
        {
            const char* src = (const char*)g_ehS + ((size_t)tile * 4) * 16384 + tid * 16;
            uint32_t dst = sb + SM_A + tid * 16;
            #pragma unroll
            for (int r = 0; r < 4; r++) CPA(dst + r * 4096, src + r * 4096);
            asm volatile("cp.async.commit_group;" ::: "memory");
        }
        if (tid < 128) ((float*)(smem + SM_E2))[tid] = g_e2[tile * 128 + tid];

        float acc[2][8][4];
        #pragma unroll
        for (int mf = 0; mf < 2; mf++)
            #pragma unroll
            for (int nf = 0; nf < 8; nf++)
                #pragma unroll
                for (int q = 0; q < 4; q++) acc[mf][nf][q] = 0.0f;

        for (int j = 0; j < 4; j++) {
            int buf = j & 1;
            asm volatile("cp.async.wait_group 0;" ::: "memory");
            __syncthreads();
            if (j < 3) {
                const char* src = (const char*)g_ehS + ((size_t)tile * 4 + j + 1) * 16384 + tid * 16;
                uint32_t dst = sb + SM_A + (buf ^ 1) * 16384u + tid * 16;
                #pragma unroll
                for (int r = 0; r < 4; r++) CPA(dst + r * 4096, src + r * 4096);
                asm volatile("cp.async.commit_group;" ::: "memory");
            }
            uint32_t bbase = sb + SM_B + (uint32_t)j * 16384u;
            uint32_t abase = sb + SM_A + (uint32_t)buf * 16384u;
            #pragma unroll
            for (int ks = 0; ks < 4; ks++) {
                uint32_t a[2][4];
                #pragma unroll
                for (int mf = 0; mf < 2; mf++) {
                    uint32_t row = mw * 32 + mf * 16 + (lane & 15);
                    uint32_t u = ((uint32_t)(ks * 2 + (lane >> 4)) ^ (row & 7));
                    uint32_t ad = abase + row * 128 + u * 16;
                    asm volatile("ldmatrix.sync.aligned.m8n8.x4.shared.b16 {%0,%1,%2,%3}, [%4];"
                        : "=r"(a[mf][0]), "=r"(a[mf][1]), "=r"(a[mf][2]), "=r"(a[mf][3]) : "r"(ad));
                }
                uint32_t bq[4][4];
                #pragma unroll
                for (int nf2 = 0; nf2 < 4; nf2++) {
                    uint32_t row = nw * 64 + nf2 * 16 + (lane & 7) + ((lane >> 4) & 1) * 8;
                    uint32_t u = ((uint32_t)(ks * 2 + ((lane >> 3) & 1)) ^ (row & 7));
                    uint32_t ad = bbase + row * 128 + u * 16;
                    asm volatile("ldmatrix.sync.aligned.m8n8.x4.shared.b16 {%0,%1,%2,%3}, [%4];"
                        : "=r"(bq[nf2][0]), "=r"(bq[nf2][1]), "=r"(bq[nf2][2]), "=r"(bq[nf2][3]) : "r"(ad));
                }
                #pragma unroll
                for (int mf = 0; mf < 2; mf++)
                    #pragma unroll
                    for (int nf = 0; nf < 8; nf++)
                        asm volatile("mma.sync.aligned.m16n8k16.row.col.f32.f16.f16.f32 "
                            "{%0,%1,%2,%3}, {%4,%5,%6,%7}, {%8,%9}, {%0,%1,%2,%3};"
                            : "+f"(acc[mf][nf][0]), "+f"(acc[mf][nf][1]),
                              "+f"(acc[mf][nf][2]), "+f"(acc[mf][nf][3])
                            : "r"(a[mf][0]), "r"(a[mf][1]), "r"(a[mf][2]), "r"(a[mf][3]),
                              "r"(bq[nf >> 1][(nf & 1) * 2]), "r"(bq[nf >> 1][(nf & 1) * 2 + 1]));
            }
        }

        const float* e2s = (const float*)(smem + SM_E2);
        int g = lane >> 2;
        #pragma unroll
        for (int nf = 0; nf < 8; nf++) {
            #pragma unroll
            for (int bb2 = 0; bb2 < 2; bb2++) {
                float m1 = 3.4e38f, m2 = 3.4e38f; int id = 0;
                #pragma unroll
                for (int mf = 0; mf < 2; mf++)
                    #pragma unroll
                    for (int rr = 0; rr < 2; rr++) {
                        int cl = mw * 32 + mf * 16 + rr * 8 + g;
                        float dist = fmaf(-2.0f, acc[mf][nf][rr * 2 + bb2], e2s[cl]);
                        int code = tile * 128 + cl;
                        if (dist < m1) { m2 = m1; m1 = dist; id = code; }
                        else if (dist < m2) m2 = dist;
                    }
                #pragma unroll
                for (int o = 4; o <= 16; o <<= 1) {
                    float am1 = __shfl_xor_sync(0xffffffffu, m1, o);
                    float am2 = __shfl_xor_sync(0xffffffffu, m2, o);
                    int   ai  = __shfl_xor_sync(0xffffffffu, id, o);
                    if (am1 < m1 || (am1 == m1 && ai < id)) { m2 = fminf(m1, am2); m1 = am1; id = ai; }
                    else m2 = fminf(m2, am1);
                }
                if (g == 0) {
                    int tl = nw * 64 + nf * 8 + (lane & 3) * 2 + bb2;
                    ((float*)(smem + SM_PM1))[mw * 128 + tl] = m1;
                    ((float*)(smem + SM_PM2))[mw * 128 + tl] = m2;
                    ((int*)(smem + SM_PID))[mw * 128 + tl]   = id;
                }
            }
        }
        __syncthreads();
        if (tid < 128) {
            float m1 = ((float*)(smem + SM_RM1))[tid], m2 = ((float*)(smem + SM_RM2))[tid];
            int id = ((int*)(smem + SM_RID))[tid];
            #pragma unroll
            for (int w = 0; w < 4; w++) {
                float am1 = ((float*)(smem + SM_PM1))[w * 128 + tid];
                float am2 = ((float*)(smem + SM_PM2))[w * 128 + tid];
                int   ai  = ((int*)(smem + SM_PID))[w * 128 + tid];
                if (am1 < m1 || (am1 == m1 && ai < id)) { m2 = fminf(m1, am2); m1 = am1; id = ai; }
                else m2 = fminf(m2, am1);
            }
            ((float*)(smem + SM_RM1))[tid] = m1;
            ((float*)(smem + SM_RM2))[tid] = m2;
            ((int*)(smem + SM_RID))[tid]   = id;
        }
        __syncthreads();
    }

    if (tid < 128) {
        int token = token0 + tid;
        g_idx[token] = ((int*)(smem + SM_RID))[tid];
        float mar = ((float*)(smem + SM_RM2))[tid] - ((float*)(smem + SM_RM1))[tid];
        if (mar < TAU1) {
            int p = atomicAdd(&g_rc1, 1);
            if (p < RESC_CAP) g_rl1[p] = token;
        }
    }
}

// ---- fp32 grouped rescue v3: smem e-tiles + packed f32x2 FMA ----
#define RT 16
__global__ __launch_bounds__(256)
void rescue32_kernel(const float* __restrict__ x, const float* __restrict__ embed)
{
    __shared__ float2 xsp[8][DIM];     // {tok p, tok p+8} per d ; 16KB
    __shared__ float  se[32][256];     // e-tile: 32 d x 256 codes ; 32KB
    __shared__ int    toks[RT];
    __shared__ float  sm1[8][RT], sm2[8][RT];
    __shared__ int    sid[8][RT];
    int tid = threadIdx.x, lane = tid & 31, wp = tid >> 5;
    int cnt = g_rc1; if (cnt > RESC_CAP) cnt = RESC_CAP;
    const unsigned long long NEG1P = 0xBF800000BF800000ULL;

    for (int g0 = blockIdx.x * RT; g0 < cnt; g0 += gridDim.x * RT) {
        int ntk = cnt - g0; if (ntk > RT) ntk = RT;
        __syncthreads();
        if (tid < ntk) toks[tid] = g_rl1[g0 + tid];
        __syncthreads();
        for (int t = 0; t < ntk; t++) {
            int tok = toks[t], b = tok >> 12, hw = tok & 4095;
            ((float*)&xsp[t & 7][tid])[t >> 3] =
                x[((size_t)b * DIM + tid) * HW + hw];
        }

        float m1[RT], m2[RT]; int id[RT];
        #pragma unroll
        for (int t = 0; t < RT; t++) { m1[t] = 3.4e38f; m2[t] = 3.4e38f; id[t] = 0; }

        for (int r = 0; r < 4; r++) {
            unsigned long long acc[8];
            #pragma unroll
            for (int p = 0; p < 8; p++) acc[p] = 0ull;
            for (int dc = 0; dc < 8; dc++) {
                __syncthreads();     // prev compute done (and xsp ready at dc=0)
                #pragma unroll 4
                for (int q = 0; q < 32; q++)
                    se[q][tid] = embed[(size_t)(dc * 32 + q) * NCODE + r * 256 + tid];
                __syncthreads();
                #pragma unroll 4
                for (int dl = 0; dl < 32; dl++) {
                    float e = se[dl][tid];
                    unsigned long long ep;
                    asm("mov.b64 %0, {%1,%1};" : "=l"(ep) : "r"(__float_as_uint(e)));
                    int dd = dc * 32 + dl;
                    #pragma unroll
                    for (int p = 0; p < 8; p++) {
                        unsigned long long xp = *(const unsigned long long*)&xsp[p][dd];
                        unsigned long long df;
                        asm("fma.rn.f32x2 %0, %1, %2, %3;"
                            : "=l"(df) : "l"(ep), "l"(NEG1P), "l"(xp));
                        asm("fma.rn.f32x2 %0, %1, %2, %0;"
                            : "+l"(acc[p]) : "l"(df), "l"(df));
                    }
                }
            }
            int k = r * 256 + tid;
            #pragma unroll
            for (int p = 0; p < 8; p++) {
                float lo = __uint_as_float((unsigned)(acc[p] & 0xffffffffull));
                float hi = __uint_as_float((unsigned)(acc[p] >> 32));
                if (lo < m1[p]) { m2[p] = m1[p]; m1[p] = lo; id[p] = k; }
                else if (lo < m2[p]) m2[p] = lo;
                int t8 = p + 8;
                if (hi < m1[t8]) { m2[t8] = m1[t8]; m1[t8] = hi; id[t8] = k; }
                else if (hi < m2[t8]) m2[t8] = hi;
            }
        }

        // warp top-2 butterfly, then cross-warp merge
        #pragma unroll
        for (int t = 0; t < RT; t++) {
            #pragma unroll
            for (int o = 16; o > 0; o >>= 1) {
                float am1 = __shfl_xor_sync(0xffffffffu, m1[t], o);
                float am2 = __shfl_xor_sync(0xffffffffu, m2[t], o);
                int   ai  = __shfl_xor_sync(0xffffffffu, id[t], o);
                if (am1 < m1[t] || (am1 == m1[t] && ai < id[t])) {
                    m2[t] = fminf(m1[t], am2); m1[t] = am1; id[t] = ai;
                } else m2[t] = fminf(m2[t], am1);
            }
            if (lane == 0) { sm1[wp][t] = m1[t]; sm2[wp][t] = m2[t]; sid[wp][t] = id[t]; }
        }
        __syncthreads();
        if (tid < ntk) {
            float bm1 = sm1[0][tid], bm2 = sm2[0][tid];
            int bi = sid[0][tid];
            #pragma unroll
            for (int w = 1; w < 8; w++) {
                float a1 = sm1[w][tid], a2v = sm2[w][tid];
                int ai = sid[w][tid];
                if (a1 < bm1 || (a1 == bm1 && ai < bi)) { bm2 = fminf(bm1, a2v); bm1 = a1; bi = ai; }
                else bm2 = fminf(bm2, a1);
            }
            int tok = toks[tid];
            g_idx[tok] = bi;
            if (bm2 - bm1 < TAU2) {
                int p = atomicAdd(&g_rc2, 1);
                if (p < RESC2_CAP) g_rl2[p] = tok;
            }
        }
    }
}

// ---- fp64 exact rescue (coalesced embed reads) ----
__global__ void rescue64_kernel(const float* __restrict__ x,
                                const float* __restrict__ embed)
{
    __shared__ float  xs[DIM];
    __shared__ double rv[256];
    __shared__ int    ri[256];
    int tid = threadIdx.x;
    int cnt = g_rc2; if (cnt > RESC2_CAP) cnt = RESC2_CAP;
    for (int f = blockIdx.x; f < cnt; f += gridDim.x) {
        int tok = g_rl2[f], b = tok >> 12, hw = tok & 4095;
        __syncthreads();
        xs[tid] = x[((size_t)b * DIM + tid) * HW + hw];
        __syncthreads();
        double best = 1e300; int bi = 0;
        for (int r = 0; r < 4; r++) {
            int k = r * 256 + tid;
            const float* ek = embed + k;
            double a2 = 0.0;
            for (int d = 0; d < DIM; d++) {
                double df = (double)xs[d] - (double)ek[(size_t)d * NCODE];
                a2 += df * df;
            }
            if (a2 < best) { best = a2; bi = k; }
        }
        rv[tid] = best; ri[tid] = bi;
        __syncthreads();
        for (int s = 128; s > 0; s >>= 1) {
            if (tid < s && (rv[tid+s] < rv[tid] || (rv[tid+s] == rv[tid] && ri[tid+s] < ri[tid]))) {
                rv[tid] = rv[tid+s]; ri[tid] = ri[tid+s];
            }
            __syncthreads();
        }
        if (tid == 0) g_idx[tok] = ri[0];
        __syncthreads();
    }
}

// ---- hist + idx float output (fused) ----
__global__ void hist_kernel(float* __restrict__ out)
{
    __shared__ int h[NCODE];
    int tid = threadIdx.x;
    for (int i = tid; i < NCODE; i += 256) h[i] = 0;
    __syncthreads();
    for (int n = blockIdx.x * 256 + tid; n < N_TOK; n += gridDim.x * 256) {
        int idx = g_idx[n];
        atomicAdd(&h[idx], 1);
        out[IDX_OFF + n] = (float)idx;
    }
    __syncthreads();
    for (int i = tid; i < NCODE; i += 256)
        if (h[i]) atomicAdd(&g_cnt[i], (float)h[i]);
}

// fused: out gather + dw scatter + loss (float4)
__global__ void gather_dw_kernel(const float* __restrict__ x,
                                 const float* __restrict__ embed,
                                 float* __restrict__ out)
{
    long i4 = ((long)blockIdx.x * 256 + threadIdx.x) * 4;
    int hw = (int)(i4 & 4095);
    int c  = (int)((i4 >> 12) & 255);
    int b  = (int)(i4 >> 20);
    int n0 = (b << 12) | hw;
    int idx0 = g_idx[n0], idx1 = g_idx[n0 + 1], idx2 = g_idx[n0 + 2], idx3 = g_idx[n0 + 3];
    const float* ec = embed + (size_t)c * NCODE;
    float4 ev = make_float4(ec[idx0], ec[idx1], ec[idx2], ec[idx3]);
    float4 xv = *(const float4*)(x + i4);
    *(float4*)(out + i4) = ev;
    float* dwc = g_dw + c * NCODE;
    atomicAdd(&dwc[idx0], xv.x);
    atomicAdd(&dwc[idx1], xv.y);
    atomicAdd(&dwc[idx2], xv.z);
    atomicAdd(&dwc[idx3], xv.w);
    float d0 = ev.x - xv.x, d1 = ev.y - xv.y, d2 = ev.z - xv.z, d3 = ev.w - xv.w;
    float v = d0 * d0 + d1 * d1 + d2 * d2 + d3 * d3;
    #pragma unroll
    for (int o = 16; o > 0; o >>= 1) v += __shfl_down_sync(0xffffffffu, v, o);
    __shared__ float ws[8];
    int tid = threadIdx.x;
    if ((tid & 31) == 0) ws[tid >> 5] = v;
    __syncthreads();
    if (tid == 0) {
        float s = 0.0f;
        #pragma unroll
        for (int w = 0; w < 8; w++) s += ws[w];
        atomicAdd(&g_loss, (double)s);
    }
}

__global__ void ncs_kernel(const float* __restrict__ cluster_size,
                           float* __restrict__ out)
{
    int k = threadIdx.x;
    float ncs = cluster_size[k] * DECAY + OMD * g_cnt[k];
    out[NCS_OFF + k] = ncs;
    double v = (double)ncs;
    #pragma unroll
    for (int o = 16; o > 0; o >>= 1) v += __shfl_down_sync(0xffffffffu, v, o);
    __shared__ double ws[32];
    if ((k & 31) == 0) ws[k >> 5] = v;
    __syncthreads();
    __shared__ double n_sh;
    if (k == 0) {
        double s = 0.0;
        for (int w = 0; w < 32; w++) s += ws[w];
        n_sh = s;
        out[LOSS_OFF] = (float)(g_loss * (double)COMMIT / 33554432.0);
    }
    __syncthreads();
    double n = n_sh;
    double smoothing = n * ((double)ncs + EPSV) / (n + (double)ncs * EPSV);
    g_sinv[k] = (float)(1.0 / smoothing);
}

__global__ void ema_kernel(const float* __restrict__ ema_embed,
                           float* __restrict__ out)
{
    int i = blockIdx.x * 256 + threadIdx.x;
    float dw = g_dw[i];
    float nema = ema_embed[i] * DECAY + OMD * dw;
    out[NEMA_OFF + i] = nema;
    out[NEWEMB_OFF + i] = nema * g_sinv[i & (NCODE - 1)];
}

// ---------------------------------------------------------------------------
extern "C" void kernel_launch(void* const* d_in, const int* in_sizes, int n_in,
                              void* d_out, int out_size)
{
    const float* x            = (const float*)d_in[0];
    const float* embed        = (const float*)d_in[1];
    const float* cluster_size = (const float*)d_in[2];
    const float* ema_embed    = (const float*)d_in[3];
    float* out = (float*)d_out;

    cudaFuncSetAttribute(argmin_hmma,
                         cudaFuncAttributeMaxDynamicSharedMemorySize, SMEM_TC);

    prep_kernel     <<<1024, 256>>>();
    conv_e_kernel   <<<dim3(32, 4), dim3(32, 8)>>>(embed);
    argmin_hmma     <<<1024, 256, SMEM_TC>>>(x);
    rescue32_kernel <<<1024, 256>>>(x, embed);
    rescue64_kernel <<<256, 256>>>(x, embed);
    hist_kernel     <<<256, 256>>>(out);
    gather_dw_kernel<<<32768, 256>>>(x, embed, out);
    ncs_kernel      <<<1, 1024>>>(cluster_size, out);
    ema_kernel      <<<1024, 256>>>(ema_embed, out);
}

// round 15
// speedup vs baseline: 1.0817x; 1.0817x over previous
#include <cuda_runtime.h>
#include <cuda_fp16.h>
#include <cstdint>
#include <cstddef>

#define N_TOK 131072
#define DIM   256
#define NCODE 1024
#define HW    4096
#define DECAY 0.9f
#define OMD   0.1f
#define COMMIT 0.25f
#define EPSV  1e-5

#define LOSS_OFF   33554432
#define IDX_OFF    33554433
#define NEWEMB_OFF 33685505
#define NCS_OFF    33947649
#define NEMA_OFF   33948673

#define RESC_CAP  131072
#define RESC2_CAP 32768
#define TAU1 6e-2f
#define TAU2 4e-3f

__device__ __half g_ehS[NCODE * DIM];   // pre-swizzled blocked [tile][chunk][row][64]
__device__ float  g_eT[NCODE * DIM];    // [k][d] fp32 (for rescues)
__device__ float  g_e2[NCODE];
__device__ int    g_idx[N_TOK];
__device__ float  g_cnt[NCODE];
__device__ float  g_dw[DIM * NCODE];
__device__ double g_loss;
__device__ float  g_sinv[NCODE];
__device__ int    g_rc1, g_rl1[RESC_CAP];
__device__ int    g_rc2, g_rl2[RESC2_CAP];

__device__ __forceinline__ uint32_t s2u(const void* p) {
    uint32_t a;
    asm("{ .reg .u64 t; cvta.to.shared.u64 t, %1; cvt.u32.u64 %0, t; }" : "=r"(a) : "l"(p));
    return a;
}

// ---- prep: zero scratch ----
__global__ void prep_kernel()
{
    int i = blockIdx.x * 256 + threadIdx.x;      // 0..262143
    if (i < DIM * NCODE) g_dw[i] = 0.0f;
    if (i < NCODE) { g_cnt[i] = 0.0f; g_e2[i] = 0.0f; }
    if (i == 0) { g_loss = 0.0; g_rc1 = 0; g_rc2 = 0; }
}

// ---- embed: [d][k] -> fp16 hi pre-swizzled blocked + fp32 [k][d] + e2 ----
__global__ void conv_e_kernel(const float* __restrict__ embed)
{
    __shared__ float t[64][33];
    int k0 = blockIdx.x * 32, d0 = blockIdx.y * 64;
    int tx = threadIdx.x, ty = threadIdx.y;   // (32, 8); warp = fixed ty
    #pragma unroll
    for (int i = 0; i < 8; i++) {
        int dd = ty + 8 * i;
        t[dd][tx] = embed[(size_t)(d0 + dd) * NCODE + k0 + tx];
    }
    __syncthreads();
    #pragma unroll
    for (int i = 0; i < 4; i++) {
        int j = ty + 8 * i, c = tx, k = k0 + j, d = d0 + 2 * c;
        float v0 = t[2*c][j], v1 = t[2*c+1][j];
        g_eT[(size_t)k * DIM + d]     = v0;
        g_eT[(size_t)k * DIM + d + 1] = v1;
        __half h0 = __float2half(v0), h1 = __float2half(v1);
        uint32_t hh = (uint32_t)__half_as_ushort(h0) | ((uint32_t)__half_as_ushort(h1) << 16);
        uint32_t blk = (uint32_t)(k >> 7) * 4u + (uint32_t)(d >> 6);
        uint32_t row = (uint32_t)(k & 127);
        uint32_t off = blk * 16384u + row * 128u
                     + ((((uint32_t)(d & 63) >> 3) ^ (row & 7)) * 16u) + (uint32_t)(d & 7) * 2u;
        *(uint32_t*)((char*)g_ehS + off) = hh;
        float p = v0 * v0 + v1 * v1;
        #pragma unroll
        for (int o = 16; o > 0; o >>= 1) p += __shfl_down_sync(0xffffffffu, p, o);
        if (tx == 0) atomicAdd(&g_e2[k], p);
    }
}

// ---- HMMA argmin (single-term estimate): 128 tokens/CTA vs 1024 codes ----
#define SM_B   0
#define SM_A   65536
#define SM_E2  98304
#define SM_PM1 98816
#define SM_PM2 100864
#define SM_PID 102912
#define SM_RM1 104960
#define SM_RM2 105472
#define SM_RID 105984
#define SMEM_TC 106496

#define CPA(dst, src) \
    asm volatile("{ .reg .u64 g; cvta.to.global.u64 g, %1; cp.async.cg.shared.global [%0], [g], 16; }" \
                 :: "r"(dst), "l"(src) : "memory")

__global__ __launch_bounds__(256, 2)
void argmin_hmma(const float* __restrict__ x)
{
    extern __shared__ char smem[];
    uint32_t sb = s2u(smem);
    int tid = threadIdx.x, lane = tid & 31, wid = tid >> 5;
    int mw = wid >> 1, nw = wid & 1;
    int token0 = blockIdx.x * 128;
    int bb0 = token0 >> 12, hw0 = token0 & 4095;
    const float* xb = x + (size_t)bb0 * DIM * HW + hw0;

    {
        int tok = tid & 127, half = tid >> 7;
        for (int i = 0; i < 64; i++) {
            int d0 = half * 2 + 4 * i;
            float v0 = xb[(size_t)d0 * HW + tok];
            float v1 = xb[(size_t)(d0 + 1) * HW + tok];
            __half h0 = __float2half(v0), h1 = __float2half(v1);
            uint32_t hh = (uint32_t)__half_as_ushort(h0) | ((uint32_t)__half_as_ushort(h1) << 16);
            uint32_t off = (uint32_t)(d0 >> 6) * 16384u + (uint32_t)tok * 128u
                         + ((((uint32_t)(d0 & 63) >> 3) ^ (uint32_t)(tok & 7)) * 16u)
                         + (uint32_t)(d0 & 7) * 2u;
            *(uint32_t*)(smem + SM_B + off) = hh;
        }
    }
    if (tid < 128) {
        ((float*)(smem + SM_RM1))[tid] = 3.4e38f;
        ((float*)(smem + SM_RM2))[tid] = 3.4e38f;
        ((int*)(smem + SM_RID))[tid] = 0;
    }
    __syncthreads();

    for (int tile = 0; tile < 8; tile++) {
        {
            const char* src = (const char*)g_ehS + ((size_t)tile * 4) * 16384 + tid * 16;
            uint32_t dst = sb + SM_A + tid * 16;
            #pragma unroll
            for (int r = 0; r < 4; r++) CPA(dst + r * 4096, src + r * 4096);
            asm volatile("cp.async.commit_group;" ::: "memory");
        }
        if (tid < 128) ((float*)(smem + SM_E2))[tid] = g_e2[tile * 128 + tid];

        float acc[2][8][4];
        #pragma unroll
        for (int mf = 0; mf < 2; mf++)
            #pragma unroll
            for (int nf = 0; nf < 8; nf++)
                #pragma unroll
                for (int q = 0; q < 4; q++) acc[mf][nf][q] = 0.0f;

        for (int j = 0; j < 4; j++) {
            int buf = j & 1;
            asm volatile("cp.async.wait_group 0;" ::: "memory");
            __syncthreads();
            if (j < 3) {
                const char* src = (const char*)g_ehS + ((size_t)tile * 4 + j + 1) * 16384 + tid * 16;
                uint32_t dst = sb + SM_A + (buf ^ 1) * 16384u + tid * 16;
                #pragma unroll
                for (int r = 0; r < 4; r++) CPA(dst + r * 4096, src + r * 4096);
                asm volatile("cp.async.commit_group;" ::: "memory");
            }
            uint32_t bbase = sb + SM_B + (uint32_t)j * 16384u;
            uint32_t abase = sb + SM_A + (uint32_t)buf * 16384u;
            #pragma unroll
            for (int ks = 0; ks < 4; ks++) {
                uint32_t a[2][4];
                #pragma unroll
                for (int mf = 0; mf < 2; mf++) {
                    uint32_t row = mw * 32 + mf * 16 + (lane & 15);
                    uint32_t u = ((uint32_t)(ks * 2 + (lane >> 4)) ^ (row & 7));
                    uint32_t ad = abase + row * 128 + u * 16;
                    asm volatile("ldmatrix.sync.aligned.m8n8.x4.shared.b16 {%0,%1,%2,%3}, [%4];"
                        : "=r"(a[mf][0]), "=r"(a[mf][1]), "=r"(a[mf][2]), "=r"(a[mf][3]) : "r"(ad));
                }
                uint32_t bq[4][4];
                #pragma unroll
                for (int nf2 = 0; nf2 < 4; nf2++) {
                    uint32_t row = nw * 64 + nf2 * 16 + (lane & 7) + ((lane >> 4) & 1) * 8;
                    uint32_t u = ((uint32_t)(ks * 2 + ((lane >> 3) & 1)) ^ (row & 7));
                    uint32_t ad = bbase + row * 128 + u * 16;
                    asm volatile("ldmatrix.sync.aligned.m8n8.x4.shared.b16 {%0,%1,%2,%3}, [%4];"
                        : "=r"(bq[nf2][0]), "=r"(bq[nf2][1]), "=r"(bq[nf2][2]), "=r"(bq[nf2][3]) : "r"(ad));
                }
                #pragma unroll
                for (int mf = 0; mf < 2; mf++)
                    #pragma unroll
                    for (int nf = 0; nf < 8; nf++)
                        asm volatile("mma.sync.aligned.m16n8k16.row.col.f32.f16.f16.f32 "
                            "{%0,%1,%2,%3}, {%4,%5,%6,%7}, {%8,%9}, {%0,%1,%2,%3};"
                            : "+f"(acc[mf][nf][0]), "+f"(acc[mf][nf][1]),
                              "+f"(acc[mf][nf][2]), "+f"(acc[mf][nf][3])
                            : "r"(a[mf][0]), "r"(a[mf][1]), "r"(a[mf][2]), "r"(a[mf][3]),
                              "r"(bq[nf >> 1][(nf & 1) * 2]), "r"(bq[nf >> 1][(nf & 1) * 2 + 1]));
            }
        }

        const float* e2s = (const float*)(smem + SM_E2);
        int g = lane >> 2;
        #pragma unroll
        for (int nf = 0; nf < 8; nf++) {
            #pragma unroll
            for (int bb2 = 0; bb2 < 2; bb2++) {
                float m1 = 3.4e38f, m2 = 3.4e38f; int id = 0;
                #pragma unroll
                for (int mf = 0; mf < 2; mf++)
                    #pragma unroll
                    for (int rr = 0; rr < 2; rr++) {
                        int cl = mw * 32 + mf * 16 + rr * 8 + g;
                        float dist = fmaf(-2.0f, acc[mf][nf][rr * 2 + bb2], e2s[cl]);
                        int code = tile * 128 + cl;
                        if (dist < m1) { m2 = m1; m1 = dist; id = code; }
                        else if (dist < m2) m2 = dist;
                    }
                #pragma unroll
                for (int o = 4; o <= 16; o <<= 1) {
                    float am1 = __shfl_xor_sync(0xffffffffu, m1, o);
                    float am2 = __shfl_xor_sync(0xffffffffu, m2, o);
                    int   ai  = __shfl_xor_sync(0xffffffffu, id, o);
                    if (am1 < m1 || (am1 == m1 && ai < id)) { m2 = fminf(m1, am2); m1 = am1; id = ai; }
                    else m2 = fminf(m2, am1);
                }
                if (g == 0) {
                    int tl = nw * 64 + nf * 8 + (lane & 3) * 2 + bb2;
                    ((float*)(smem + SM_PM1))[mw * 128 + tl] = m1;
                    ((float*)(smem + SM_PM2))[mw * 128 + tl] = m2;
                    ((int*)(smem + SM_PID))[mw * 128 + tl]   = id;
                }
            }
        }
        __syncthreads();
        if (tid < 128) {
            float m1 = ((float*)(smem + SM_RM1))[tid], m2 = ((float*)(smem + SM_RM2))[tid];
            int id = ((int*)(smem + SM_RID))[tid];
            #pragma unroll
            for (int w = 0; w < 4; w++) {
                float am1 = ((float*)(smem + SM_PM1))[w * 128 + tid];
                float am2 = ((float*)(smem + SM_PM2))[w * 128 + tid];
                int   ai  = ((int*)(smem + SM_PID))[w * 128 + tid];
                if (am1 < m1 || (am1 == m1 && ai < id)) { m2 = fminf(m1, am2); m1 = am1; id = ai; }
                else m2 = fminf(m2, am1);
            }
            ((float*)(smem + SM_RM1))[tid] = m1;
            ((float*)(smem + SM_RM2))[tid] = m2;
            ((int*)(smem + SM_RID))[tid]   = id;
        }
        __syncthreads();
    }

    if (tid < 128) {
        int token = token0 + tid;
        g_idx[token] = ((int*)(smem + SM_RID))[tid];
        float mar = ((float*)(smem + SM_RM2))[tid] - ((float*)(smem + SM_RM1))[tid];
        if (mar < TAU1) {
            int p = atomicAdd(&g_rc1, 1);
            if (p < RESC_CAP) g_rl1[p] = token;
        }
    }
}

// ---- fp32 grouped rescue (R9-proven: 16 tokens/block, float4 g_eT reads) ----
#define RT 16
__global__ __launch_bounds__(256)
void rescue32_kernel(const float* __restrict__ x)
{
    __shared__ float xs[RT][DIM];
    __shared__ int   toks[RT];
    __shared__ float rA[RT * 256], rB[RT * 256];
    __shared__ int   rI[RT * 256];
    int tid = threadIdx.x;
    int cnt = g_rc1; if (cnt > RESC_CAP) cnt = RESC_CAP;

    for (int g0 = blockIdx.x * RT; g0 < cnt; g0 += gridDim.x * RT) {
        int ntk = cnt - g0; if (ntk > RT) ntk = RT;
        __syncthreads();
        if (tid < ntk) toks[tid] = g_rl1[g0 + tid];
        __syncthreads();
        for (int t = 0; t < ntk; t++) {
            int tok = toks[t], b = tok >> 12, hw = tok & 4095;
            xs[t][tid] = x[((size_t)b * DIM + tid) * HW + hw];
        }
        __syncthreads();

        float m1[RT], m2[RT]; int id[RT];
        #pragma unroll
        for (int t = 0; t < RT; t++) { m1[t] = 3.4e38f; m2[t] = 3.4e38f; id[t] = 0; }
        for (int r = 0; r < 4; r++) {
            int k = r * 256 + tid;
            const float* er = g_eT + (size_t)k * DIM;
            float a2[RT];
            #pragma unroll
            for (int t = 0; t < RT; t++) a2[t] = 0.0f;
            for (int d = 0; d < DIM; d += 4) {
                float4 e4 = *(const float4*)(er + d);
                #pragma unroll
                for (int t = 0; t < RT; t++) {
                    float d0 = xs[t][d]     - e4.x;
                    float d1 = xs[t][d + 1] - e4.y;
                    float d2 = xs[t][d + 2] - e4.z;
                    float d3 = xs[t][d + 3] - e4.w;
                    a2[t] = fmaf(d0, d0, a2[t]);
                    a2[t] = fmaf(d1, d1, a2[t]);
                    a2[t] = fmaf(d2, d2, a2[t]);
                    a2[t] = fmaf(d3, d3, a2[t]);
                }
            }
            #pragma unroll
            for (int t = 0; t < RT; t++) {
                if (a2[t] < m1[t]) { m2[t] = m1[t]; m1[t] = a2[t]; id[t] = k; }
                else if (a2[t] < m2[t]) m2[t] = a2[t];
            }
        }
        #pragma unroll
        for (int t = 0; t < RT; t++) {
            rA[t * 256 + tid] = m1[t]; rB[t * 256 + tid] = m2[t]; rI[t * 256 + tid] = id[t];
        }
        __syncthreads();
        if (tid < ntk) {
            float bm1 = rA[tid * 256], bm2 = rB[tid * 256];
            int bi = rI[tid * 256];
            for (int q = 1; q < 256; q++) {
                float a1 = rA[tid * 256 + q], a2v = rB[tid * 256 + q];
                int ai = rI[tid * 256 + q];
                if (a1 < bm1 || (a1 == bm1 && ai < bi)) { bm2 = fminf(bm1, a2v); bm1 = a1; bi = ai; }
                else bm2 = fminf(bm2, a1);
            }
            int tok = toks[tid];
            g_idx[tok] = bi;
            if (bm2 - bm1 < TAU2) {
                int p = atomicAdd(&g_rc2, 1);
                if (p < RESC2_CAP) g_rl2[p] = tok;
            }
        }
    }
}

// ---- fp64 exact rescue (R9-proven) ----
__global__ void rescue64_kernel(const float* __restrict__ x)
{
    __shared__ float  xs[DIM];
    __shared__ double rv[256];
    __shared__ int    ri[256];
    int tid = threadIdx.x;
    int cnt = g_rc2; if (cnt > RESC2_CAP) cnt = RESC2_CAP;
    for (int f = blockIdx.x; f < cnt; f += gridDim.x) {
        int tok = g_rl2[f], b = tok >> 12, hw = tok & 4095;
        __syncthreads();
        xs[tid] = x[((size_t)b * DIM + tid) * HW + hw];
        __syncthreads();
        double best = 1e300; int bi = 0;
        for (int r = 0; r < 4; r++) {
            int k = r * 256 + tid;
            const float* er = g_eT + (size_t)k * DIM;
            double a2 = 0.0;
            for (int d = 0; d < DIM; d++) {
                double df = (double)xs[d] - (double)er[d];
                a2 += df * df;
            }
            if (a2 < best) { best = a2; bi = k; }
        }
        rv[tid] = best; ri[tid] = bi;
        __syncthreads();
        for (int s = 128; s > 0; s >>= 1) {
            if (tid < s && (rv[tid+s] < rv[tid] || (rv[tid+s] == rv[tid] && ri[tid+s] < ri[tid]))) {
                rv[tid] = rv[tid+s]; ri[tid] = ri[tid+s];
            }
            __syncthreads();
        }
        if (tid == 0) g_idx[tok] = ri[0];
        __syncthreads();
    }
}

// ---- hist + idx float output (fused) ----
__global__ void hist_kernel(float* __restrict__ out)
{
    __shared__ int h[NCODE];
    int tid = threadIdx.x;
    for (int i = tid; i < NCODE; i += 256) h[i] = 0;
    __syncthreads();
    for (int n = blockIdx.x * 256 + tid; n < N_TOK; n += gridDim.x * 256) {
        int idx = g_idx[n];
        atomicAdd(&h[idx], 1);
        out[IDX_OFF + n] = (float)idx;
    }
    __syncthreads();
    for (int i = tid; i < NCODE; i += 256)
        if (h[i]) atomicAdd(&g_cnt[i], (float)h[i]);
}

// fused: out gather + dw scatter + loss (float4)
__global__ void gather_dw_kernel(const float* __restrict__ x,
                                 const float* __restrict__ embed,
                                 float* __restrict__ out)
{
    long i4 = ((long)blockIdx.x * 256 + threadIdx.x) * 4;
    int hw = (int)(i4 & 4095);
    int c  = (int)((i4 >> 12) & 255);
    int b  = (int)(i4 >> 20);
    int n0 = (b << 12) | hw;
    int idx0 = g_idx[n0], idx1 = g_idx[n0 + 1], idx2 = g_idx[n0 + 2], idx3 = g_idx[n0 + 3];
    const float* ec = embed + (size_t)c * NCODE;
    float4 ev = make_float4(ec[idx0], ec[idx1], ec[idx2], ec[idx3]);
    float4 xv = *(const float4*)(x + i4);
    *(float4*)(out + i4) = ev;
    float* dwc = g_dw + c * NCODE;
    atomicAdd(&dwc[idx0], xv.x);
    atomicAdd(&dwc[idx1], xv.y);
    atomicAdd(&dwc[idx2], xv.z);
    atomicAdd(&dwc[idx3], xv.w);
    float d0 = ev.x - xv.x, d1 = ev.y - xv.y, d2 = ev.z - xv.z, d3 = ev.w - xv.w;
    float v = d0 * d0 + d1 * d1 + d2 * d2 + d3 * d3;
    #pragma unroll
    for (int o = 16; o > 0; o >>= 1) v += __shfl_down_sync(0xffffffffu, v, o);
    __shared__ float ws[8];
    int tid = threadIdx.x;
    if ((tid & 31) == 0) ws[tid >> 5] = v;
    __syncthreads();
    if (tid == 0) {
        float s = 0.0f;
        #pragma unroll
        for (int w = 0; w < 8; w++) s += ws[w];
        atomicAdd(&g_loss, (double)s);
    }
}

__global__ void ncs_kernel(const float* __restrict__ cluster_size,
                           float* __restrict__ out)
{
    int k = threadIdx.x;
    float ncs = cluster_size[k] * DECAY + OMD * g_cnt[k];
    out[NCS_OFF + k] = ncs;
    double v = (double)ncs;
    #pragma unroll
    for (int o = 16; o > 0; o >>= 1) v += __shfl_down_sync(0xffffffffu, v, o);
    __shared__ double ws[32];
    if ((k & 31) == 0) ws[k >> 5] = v;
    __syncthreads();
    __shared__ double n_sh;
    if (k == 0) {
        double s = 0.0;
        for (int w = 0; w < 32; w++) s += ws[w];
        n_sh = s;
        out[LOSS_OFF] = (float)(g_loss * (double)COMMIT / 33554432.0);
    }
    __syncthreads();
    double n = n_sh;
    double smoothing = n * ((double)ncs + EPSV) / (n + (double)ncs * EPSV);
    g_sinv[k] = (float)(1.0 / smoothing);
}

__global__ void ema_kernel(const float* __restrict__ ema_embed,
                           float* __restrict__ out)
{
    int i = blockIdx.x * 256 + threadIdx.x;
    float dw = g_dw[i];
    float nema = ema_embed[i] * DECAY + OMD * dw;
    out[NEMA_OFF + i] = nema;
    out[NEWEMB_OFF + i] = nema * g_sinv[i & (NCODE - 1)];
}

// ---------------------------------------------------------------------------
extern "C" void kernel_launch(void* const* d_in, const int* in_sizes, int n_in,
                              void* d_out, int out_size)
{
    const float* x            = (const float*)d_in[0];
    const float* embed        = (const float*)d_in[1];
    const float* cluster_size = (const float*)d_in[2];
    const float* ema_embed    = (const float*)d_in[3];
    float* out = (float*)d_out;

    cudaFuncSetAttribute(argmin_hmma,
                         cudaFuncAttributeMaxDynamicSharedMemorySize, SMEM_TC);

    prep_kernel     <<<1024, 256>>>();
    conv_e_kernel   <<<dim3(32, 4), dim3(32, 8)>>>(embed);
    argmin_hmma     <<<1024, 256, SMEM_TC>>>(x);
    rescue32_kernel <<<512, 256>>>(x);
    rescue64_kernel <<<256, 256>>>(x);
    hist_kernel     <<<256, 256>>>(out);
    gather_dw_kernel<<<32768, 256>>>(x, embed, out);
    ncs_kernel      <<<1, 1024>>>(cluster_size, out);
    ema_kernel      <<<1024, 256>>>(ema_embed, out);
}